// round 13
// baseline (speedup 1.0000x reference)
#include <cuda_runtime.h>
#include <cuda_bf16.h>
#include <cstdint>
#include <math.h>

typedef unsigned short u16;

#define T_NEWC 2048
#define HIDC   2048
#define NHC    16
#define KVHC   2
#define HDC    128
#define T_PASTC 2048
#define T_FULLC 4096
#define KVDC   256

#define OUT0   (T_NEWC*HIDC)
#define KOFF   OUT0
#define VOFF   (OUT0 + KVHC*T_FULLC*HDC)

#define ATT_SCALE 0.08838834764831845f  // 1/sqrt(128)

#define HID2 (T_NEWC*HIDC)
#define KV_ELEMS (KVHC*T_FULLC*HDC)     // 1,048,576

// ---------------- scratch ----------------
__device__ float g_q[HID2];
__device__ float g_attn[HID2];
__device__ float g_kn[T_NEWC*KVDC];
__device__ float g_vn[T_NEWC*KVDC];
__device__ uint4 g_kt4[KV_ELEMS/4];                          // K cache, tf32 [kh][t][d]
__device__ uint4 g_vth4[KV_ELEMS/8], g_vtl4[KV_ELEMS/8];     // V^T bf16 hi/lo [kh*128+d][4096]

// ---------------- helpers ----------------
__device__ __forceinline__ unsigned pack_bf2(__nv_bfloat16 a, __nv_bfloat16 b) {
    __nv_bfloat162 t = __halves2bfloat162(a, b);
    return *reinterpret_cast<unsigned*>(&t);
}
__device__ __forceinline__ void split2(float x, float y, unsigned& hi, unsigned& lo) {
    __nv_bfloat16 xh = __float2bfloat16_rn(x);
    __nv_bfloat16 yh = __float2bfloat16_rn(y);
    __nv_bfloat16 xl = __float2bfloat16_rn(x - __bfloat162float(xh));
    __nv_bfloat16 yl = __float2bfloat16_rn(y - __bfloat162float(yh));
    hi = pack_bf2(xh, yh);
    lo = pack_bf2(xl, yl);
}
__device__ __forceinline__ void mma_bf16(float* c, const unsigned* a, unsigned b0, unsigned b1) {
    asm volatile(
        "mma.sync.aligned.m16n8k16.row.col.f32.bf16.bf16.f32 "
        "{%0,%1,%2,%3}, {%4,%5,%6,%7}, {%8,%9}, {%0,%1,%2,%3};\n"
        : "+f"(c[0]), "+f"(c[1]), "+f"(c[2]), "+f"(c[3])
        : "r"(a[0]), "r"(a[1]), "r"(a[2]), "r"(a[3]), "r"(b0), "r"(b1));
}
__device__ __forceinline__ void mma_tf32(float* c, const unsigned* a, unsigned b0, unsigned b1) {
    asm volatile(
        "mma.sync.aligned.m16n8k8.row.col.f32.tf32.tf32.f32 "
        "{%0,%1,%2,%3}, {%4,%5,%6,%7}, {%8,%9}, {%0,%1,%2,%3};\n"
        : "+f"(c[0]), "+f"(c[1]), "+f"(c[2]), "+f"(c[3])
        : "r"(a[0]), "r"(a[1]), "r"(a[2]), "r"(a[3]), "r"(b0), "r"(b1));
}
__device__ __forceinline__ unsigned f2tf32(float x) {
    unsigned r;
    asm("cvt.rna.tf32.f32 %0, %1;\n" : "=r"(r) : "f"(x));
    return r;
}
__device__ __forceinline__ unsigned su32(const void* p) {
    return (unsigned)__cvta_generic_to_shared(p);
}
__device__ __forceinline__ void cpa16(u16* dst, const void* src) {
    asm volatile("cp.async.cg.shared.global [%0], [%1], 16;\n"
                 :: "r"(su32(dst)), "l"(src));
}
#define CP_COMMIT() asm volatile("cp.async.commit_group;\n")
#define CP_WAIT0()  asm volatile("cp.async.wait_group 0;\n")

__device__ __forceinline__ void ldsm4(unsigned r[4], const u16* rowbase, int stride, int kc) {
    const int lane = threadIdx.x & 31;
    const u16* p = rowbase + (lane & 15) * stride + kc + ((lane & 16) >> 1);
    unsigned a = su32(p);
    asm volatile("ldmatrix.sync.aligned.m8n8.x4.shared.b16 {%0,%1,%2,%3}, [%4];\n"
        : "=r"(r[0]), "=r"(r[1]), "=r"(r[2]), "=r"(r[3]) : "r"(a));
}

// ---------------------------------------------------------------------------
// tf32 GEMM (proven at R9): C = A @ W^T + bias. 128 thr, 2x2 warps,
// warp tile 64x64, CTA 128x128, BK=32. Region-dispatched for fused QKV.
// ---------------------------------------------------------------------------
__global__ __launch_bounds__(128, 2) void gemm_tf32(
    const float* __restrict__ A,
    const float* __restrict__ W0, const float* __restrict__ b0, float* __restrict__ C0,
    const float* __restrict__ W1, const float* __restrict__ b1, float* __restrict__ C1,
    const float* __restrict__ W2, const float* __restrict__ b2, float* __restrict__ C2,
    int nx0, int K)
{
    __shared__ unsigned As[128*36], Bs[128*36];

    const int tid  = threadIdx.x;
    const int w    = tid >> 5;
    const int lane = tid & 31;
    const int g    = lane >> 2;
    const int tig  = lane & 3;
    const int wm   = w >> 1, wn = w & 1;
    const int bm   = blockIdx.y * 128;
    const int bx   = blockIdx.x;

    const float *W, *bias; float* C; int N, bnl;
    if (bx < nx0)            { W = W0; bias = b0; C = C0; N = nx0*128; bnl = bx*128; }
    else if (bx < nx0 + 2)   { W = W1; bias = b1; C = C1; N = 256; bnl = (bx-nx0)*128; }
    else                     { W = W2; bias = b2; C = C2; N = 256; bnl = (bx-nx0-2)*128; }
    const float* Wp = W + (size_t)bnl * K;

    float acc[4][8][4];
    #pragma unroll
    for (int mt = 0; mt < 4; mt++)
        #pragma unroll
        for (int nt = 0; nt < 8; nt++)
            #pragma unroll
            for (int c = 0; c < 4; c++) acc[mt][nt][c] = 0.f;

    for (int k0 = 0; k0 < K; k0 += 32) {
        __syncthreads();
        #pragma unroll
        for (int it = 0; it < 8; it++) {
            int i = tid + it * 128;
            int row = i >> 3;
            int col = (i & 7) * 4;
            float4 a = *(const float4*)(A + (size_t)(bm + row) * K + k0 + col);
            *(uint4*)(As + row*36 + col) =
                make_uint4(f2tf32(a.x), f2tf32(a.y), f2tf32(a.z), f2tf32(a.w));
            float4 b = *(const float4*)(Wp + (size_t)row * K + k0 + col);
            *(uint4*)(Bs + row*36 + col) =
                make_uint4(f2tf32(b.x), f2tf32(b.y), f2tf32(b.z), f2tf32(b.w));
        }
        __syncthreads();

        #pragma unroll
        for (int kc = 0; kc < 4; kc++) {
            unsigned af[4][4];
            #pragma unroll
            for (int mt = 0; mt < 4; mt++)
                ldsm4(af[mt], (const u16*)As + (wm*64 + mt*16) * 72, 72, kc*16);
            #pragma unroll
            for (int ntp = 0; ntp < 4; ntp++) {
                unsigned bf[4];
                ldsm4(bf, (const u16*)Bs + (wn*64 + ntp*16) * 72, 72, kc*16);
                #pragma unroll
                for (int mt = 0; mt < 4; mt++) {
                    mma_tf32(acc[mt][2*ntp],   af[mt], bf[0], bf[2]);
                    mma_tf32(acc[mt][2*ntp+1], af[mt], bf[1], bf[3]);
                }
            }
        }
    }

    #pragma unroll
    for (int mt = 0; mt < 4; mt++) {
        #pragma unroll
        for (int nt = 0; nt < 8; nt++) {
            int row = bm + wm*64 + mt*16 + g;
            int col = bnl + wn*64 + nt*8 + 2*tig;
            float bb0 = bias[col], bb1 = bias[col+1];
            *(float2*)(C + (size_t)row * N + col) =
                make_float2(acc[mt][nt][0] + bb0, acc[mt][nt][1] + bb1);
            *(float2*)(C + (size_t)(row+8) * N + col) =
                make_float2(acc[mt][nt][2] + bb0, acc[mt][nt][3] + bb1);
        }
    }
}

// ---------------------------------------------------------------------------
// prep_k: concat K cache -> out fp32 + tf32 K cache (cvt.rna once)
// ---------------------------------------------------------------------------
__global__ __launch_bounds__(256) void prep_k(
    const float* __restrict__ pk, float* __restrict__ out)
{
    const int tid = threadIdx.x;
    const int h   = blockIdx.y;
    const int t0  = blockIdx.x * 64;
    unsigned* kt = (unsigned*)g_kt4;

    #pragma unroll
    for (int it = 0; it < 8; it++) {
        int i = tid + it * 256;
        int row = i >> 5, seg = i & 31;
        int t = t0 + row, d = seg * 4;
        float4 k4;
        if (t < T_PASTC) {
            k4 = *(const float4*)(pk + ((size_t)h * T_PASTC + t) * HDC + d);
        } else {
            k4 = *(const float4*)(g_kn + (size_t)(t - T_PASTC) * KVDC + h * HDC + d);
        }
        size_t oidx = ((size_t)h * T_FULLC + t) * HDC + d;
        *(float4*)(out + KOFF + oidx) = k4;
        *(uint4*)(kt + oidx) =
            make_uint4(f2tf32(k4.x), f2tf32(k4.y), f2tf32(k4.z), f2tf32(k4.w));
    }
}

// ---------------------------------------------------------------------------
// prep_v (unchanged, proven): concat V -> out fp32 + transposed bf16 hi/lo V^T
// ---------------------------------------------------------------------------
__global__ __launch_bounds__(256) void prep_v(
    const float* __restrict__ pv, float* __restrict__ out)
{
    __shared__ float Vsm[64][129];
    const int tid = threadIdx.x;
    const int h   = blockIdx.y;
    const int t0  = blockIdx.x * 64;
    uint2* vth = (uint2*)g_vth4;
    uint2* vtl = (uint2*)g_vtl4;

    #pragma unroll
    for (int it = 0; it < 8; it++) {
        int i = tid + it * 256;
        int row = i >> 5, seg = i & 31;
        int t = t0 + row, d = seg * 4;
        float4 v4;
        if (t < T_PASTC) {
            v4 = *(const float4*)(pv + ((size_t)h * T_PASTC + t) * HDC + d);
        } else {
            v4 = *(const float4*)(g_vn + (size_t)(t - T_PASTC) * KVDC + h * HDC + d);
        }
        size_t oidx = ((size_t)h * T_FULLC + t) * HDC + d;
        *(float4*)(out + VOFF + oidx) = v4;
        Vsm[row][d]   = v4.x; Vsm[row][d+1] = v4.y;
        Vsm[row][d+2] = v4.z; Vsm[row][d+3] = v4.w;
    }
    __syncthreads();

    #pragma unroll
    for (int it = 0; it < 16; it++) {
        int i = tid + it * 256;
        int split = i >> 11;
        int d = (i >> 4) & 127;
        int seg = i & 15;
        int tl = seg * 4;
        float v0 = Vsm[tl+0][d], v1 = Vsm[tl+1][d], v2 = Vsm[tl+2][d], v3 = Vsm[tl+3][d];
        unsigned h0, l0, h1, l1;
        split2(v0, v1, h0, l0);
        split2(v2, v3, h1, l1);
        size_t oidx = ((size_t)(h*128 + d) * T_FULLC + t0 + tl) >> 2;
        if (split == 0) vth[oidx] = make_uint2(h0, h1);
        else            vtl[oidx] = make_uint2(l0, l1);
    }
}

// ---------------------------------------------------------------------------
// Flash v4: tf32 S-stage (single pass), bf16x3 PV, BM=64, BN=64, 4 warps,
// 2 CTA/SM, 3-buffer cp.async ring.
// K tile: 64 rows x 136 fp32 (stride 272 halves), 34816 B.
// V tile: bf16 hi/lo as before, 36864 B.
// ---------------------------------------------------------------------------
#define FL3_BUF   18432                 // u16 per ring buffer (36,864 B)
#define FL3_BYTES (3*FL3_BUF*2)

__device__ __forceinline__ void fl4_load_k(u16* dst, int kh, int n0, int tid) {
    const unsigned* Kt = (const unsigned*)g_kt4;
    #pragma unroll
    for (int it = 0; it < 16; it++) {
        int i = tid + it * 128;          // 0..2047 16B chunks
        int row = i >> 5, seg = i & 31;
        const unsigned* src = Kt + (((size_t)(kh * T_FULLC + n0 + row)) << 7) + seg * 4;
        cpa16(dst + row * 272 + seg * 8, src);
    }
}
__device__ __forceinline__ void fl4_load_v(u16* dst, int kh, int n0, int tid) {
    const u16* Vh_g = (const u16*)g_vth4;
    const u16* Vl_g = (const u16*)g_vtl4;
    #pragma unroll
    for (int it = 0; it < 16; it++) {
        int i = tid + it * 128;
        int split = i >> 10;
        int j = i & 1023;
        int row = j >> 3, seg = j & 7;
        const u16* src = (split ? Vl_g : Vh_g)
                         + (((size_t)(kh * 128 + row)) << 12) + n0 + seg * 8;
        cpa16(dst + split * 9216 + row * 72 + seg * 8, src);
    }
}

__global__ __launch_bounds__(128, 2) void flash4()
{
    extern __shared__ u16 fsm[];
    u16* bufs[3] = { fsm, fsm + FL3_BUF, fsm + 2*FL3_BUF };

    const int tid  = threadIdx.x;
    const int w    = tid >> 5;
    const int lane = tid & 31;
    const int g    = lane >> 2;
    const int tig  = lane & 3;
    const int qi = (int)(gridDim.x - 1) - (int)blockIdx.x;   // heavy tiles first
    const int h  = blockIdx.y;
    const int qbase = qi * 64;
    const int kh = h >> 3;
    const int nkt = 33 + qi;

    // ---- stage Q (scaled, tf32) into bufs[0], extract 16 k8 fragments ----
    #pragma unroll
    for (int it = 0; it < 16; it++) {
        int i = tid + it * 128;
        int row = i >> 5, d = (i & 31) * 4;
        float4 q4 = *(const float4*)(g_q + (size_t)(qbase + row) * HIDC + h * HDC + d);
        *(uint4*)(bufs[0] + row*272 + d*2) =
            make_uint4(f2tf32(q4.x * ATT_SCALE), f2tf32(q4.y * ATT_SCALE),
                       f2tf32(q4.z * ATT_SCALE), f2tf32(q4.w * ATT_SCALE));
    }
    __syncthreads();
    unsigned qf[16][4];
    #pragma unroll
    for (int kc = 0; kc < 16; kc++)
        ldsm4(qf[kc], bufs[0] + (w*16) * 272, 272, kc * 16);
    __syncthreads();

    // ---- preload K(0)->buf0, V(0)->buf1 ----
    fl4_load_k(bufs[0], kh, 0, tid);
    fl4_load_v(bufs[1], kh, 0, tid);
    CP_COMMIT();

    float accO[16][4];
    #pragma unroll
    for (int dt = 0; dt < 16; dt++)
        #pragma unroll
        for (int c = 0; c < 4; c++) accO[dt][c] = 0.f;
    float m0 = -INFINITY, m1 = -INFINITY, l0s = 0.f, l1s = 0.f;

    int kbi = 0;
    for (int kt = 0; kt < nkt; kt++) {
        const u16* KB = bufs[kbi];
        const int vbi = (kbi + 1) % 3;
        const u16* VB = bufs[vbi];

        CP_WAIT0();
        __syncthreads();

        // ---- S = Q K^T (tf32 single pass: 16 k8 chunks) ----
        float s[8][4];
        #pragma unroll
        for (int nt = 0; nt < 8; nt++)
            #pragma unroll
            for (int c = 0; c < 4; c++) s[nt][c] = 0.f;

        #pragma unroll
        for (int kc = 0; kc < 16; kc++) {
            #pragma unroll
            for (int ntp = 0; ntp < 4; ntp++) {
                unsigned kf[4];
                ldsm4(kf, KB + ntp*16 * 272, 272, kc * 16);
                mma_tf32(s[2*ntp],   qf[kc], kf[0], kf[2]);
                mma_tf32(s[2*ntp+1], qf[kc], kf[1], kf[3]);
            }
        }
        __syncthreads();   // all warps done reading K(t)

        // ---- prefetch K(t+1), V(t+1) ----
        if (kt + 1 < nkt) {
            int kbn = (kbi + 2) % 3;
            fl4_load_k(bufs[kbn], kh, (kt + 1) * 64, tid);
            fl4_load_v(bufs[kbi], kh, (kt + 1) * 64, tid);
            CP_COMMIT();
        }

        // ---- causal mask (diagonal tile) ----
        if (kt == nkt - 1) {
            int r0 = w*16 + g, r1 = r0 + 8;
            #pragma unroll
            for (int nt = 0; nt < 8; nt++) {
                int cb = nt*8 + 2*tig;
                if (cb     > r0) s[nt][0] = -1e30f;
                if (cb + 1 > r0) s[nt][1] = -1e30f;
                if (cb     > r1) s[nt][2] = -1e30f;
                if (cb + 1 > r1) s[nt][3] = -1e30f;
            }
        }

        // ---- online softmax (registers) ----
        float mx0 = -1e30f, mx1 = -1e30f;
        #pragma unroll
        for (int nt = 0; nt < 8; nt++) {
            mx0 = fmaxf(mx0, fmaxf(s[nt][0], s[nt][1]));
            mx1 = fmaxf(mx1, fmaxf(s[nt][2], s[nt][3]));
        }
        mx0 = fmaxf(mx0, __shfl_xor_sync(0xffffffffu, mx0, 1));
        mx0 = fmaxf(mx0, __shfl_xor_sync(0xffffffffu, mx0, 2));
        mx1 = fmaxf(mx1, __shfl_xor_sync(0xffffffffu, mx1, 1));
        mx1 = fmaxf(mx1, __shfl_xor_sync(0xffffffffu, mx1, 2));
        float mn0 = fmaxf(m0, mx0), mn1 = fmaxf(m1, mx1);
        float f0 = __expf(m0 - mn0), f1 = __expf(m1 - mn1);
        float sum0 = 0.f, sum1 = 0.f;
        #pragma unroll
        for (int nt = 0; nt < 8; nt++) {
            s[nt][0] = __expf(s[nt][0] - mn0); sum0 += s[nt][0];
            s[nt][1] = __expf(s[nt][1] - mn0); sum0 += s[nt][1];
            s[nt][2] = __expf(s[nt][2] - mn1); sum1 += s[nt][2];
            s[nt][3] = __expf(s[nt][3] - mn1); sum1 += s[nt][3];
        }
        sum0 += __shfl_xor_sync(0xffffffffu, sum0, 1);
        sum0 += __shfl_xor_sync(0xffffffffu, sum0, 2);
        sum1 += __shfl_xor_sync(0xffffffffu, sum1, 1);
        sum1 += __shfl_xor_sync(0xffffffffu, sum1, 2);
        l0s = l0s * f0 + sum0;
        l1s = l1s * f1 + sum1;
        m0 = mn0; m1 = mn1;

        #pragma unroll
        for (int dt = 0; dt < 16; dt++) {
            accO[dt][0] *= f0; accO[dt][1] *= f0;
            accO[dt][2] *= f1; accO[dt][3] *= f1;
        }

        // ---- O += P V  (bf16x3, per-kc2 phi/plo) ----
        #pragma unroll
        for (int kc2 = 0; kc2 < 4; kc2++) {
            unsigned phi[4], plo[4];
            split2(s[2*kc2][0],   s[2*kc2][1],   phi[0], plo[0]);
            split2(s[2*kc2][2],   s[2*kc2][3],   phi[1], plo[1]);
            split2(s[2*kc2+1][0], s[2*kc2+1][1], phi[2], plo[2]);
            split2(s[2*kc2+1][2], s[2*kc2+1][3], phi[3], plo[3]);
            #pragma unroll
            for (int dtp = 0; dtp < 8; dtp++) {
                unsigned vh[4], vl[4];
                ldsm4(vh, VB + dtp*16 * 72, 72, kc2 * 16);
                ldsm4(vl, VB + 9216 + dtp*16 * 72, 72, kc2 * 16);
                mma_bf16(accO[2*dtp],   phi, vh[0], vh[2]);
                mma_bf16(accO[2*dtp],   phi, vl[0], vl[2]);
                mma_bf16(accO[2*dtp],   plo, vh[0], vh[2]);
                mma_bf16(accO[2*dtp+1], phi, vh[1], vh[3]);
                mma_bf16(accO[2*dtp+1], phi, vl[1], vl[3]);
                mma_bf16(accO[2*dtp+1], plo, vh[1], vh[3]);
            }
        }
        kbi = (kbi + 2) % 3;
    }

    float inv0 = 1.f / l0s, inv1 = 1.f / l1s;
    int row0 = qbase + w*16 + g;
    #pragma unroll
    for (int dt = 0; dt < 16; dt++) {
        int col = h * HDC + dt*8 + 2*tig;
        *(float2*)(g_attn + (size_t)row0 * HIDC + col) =
            make_float2(accO[dt][0] * inv0, accO[dt][1] * inv0);
        *(float2*)(g_attn + (size_t)(row0+8) * HIDC + col) =
            make_float2(accO[dt][2] * inv1, accO[dt][3] * inv1);
    }
}

// ---------------------------------------------------------------------------
extern "C" void kernel_launch(void* const* d_in, const int* in_sizes, int n_in,
                              void* d_out, int out_size)
{
    const float* hs     = (const float*)d_in[0];
    const float* past_k = (const float*)d_in[2];
    const float* past_v = (const float*)d_in[3];
    const float* q_w    = (const float*)d_in[4];
    const float* q_b    = (const float*)d_in[5];
    const float* k_w    = (const float*)d_in[6];
    const float* k_b    = (const float*)d_in[7];
    const float* v_w    = (const float*)d_in[8];
    const float* v_b    = (const float*)d_in[9];
    const float* o_w    = (const float*)d_in[10];
    const float* o_b    = (const float*)d_in[11];
    float* out = (float*)d_out;

    void *gq, *gattn, *gkn, *gvn;
    cudaGetSymbolAddress(&gq,  g_q);   cudaGetSymbolAddress(&gattn, g_attn);
    cudaGetSymbolAddress(&gkn, g_kn);  cudaGetSymbolAddress(&gvn,  g_vn);

    cudaFuncSetAttribute(flash4, cudaFuncAttributeMaxDynamicSharedMemorySize, FL3_BYTES);

    // [1] fused Q/K/V projections (tf32)
    gemm_tf32<<<dim3(20, 16), 128>>>(
        hs,
        q_w, q_b, (float*)gq,
        k_w, k_b, (float*)gkn,
        v_w, v_b, (float*)gvn,
        16, HIDC);

    // [2][3] KV concat + caches (K -> tf32, V -> bf16 hi/lo transposed)
    prep_k<<<dim3(T_FULLC/64, KVHC), 256>>>(past_k, out);
    prep_v<<<dim3(T_FULLC/64, KVHC), 256>>>(past_v, out);

    // [4] attention (tf32 S, bf16x3 PV)
    flash4<<<dim3(T_NEWC/64, NHC), 128, FL3_BYTES>>>();

    // [5] O projection (tf32)
    gemm_tf32<<<dim3(16, 16), 128>>>(
        (const float*)gattn,
        o_w, o_b, out,
        nullptr, nullptr, nullptr,
        nullptr, nullptr, nullptr,
        16, HIDC);
}

// round 14
// speedup vs baseline: 1.0026x; 1.0026x over previous
#include <cuda_runtime.h>
#include <cuda_bf16.h>
#include <cstdint>
#include <math.h>

typedef unsigned short u16;

#define T_NEWC 2048
#define HIDC   2048
#define NHC    16
#define KVHC   2
#define HDC    128
#define T_PASTC 2048
#define T_FULLC 4096
#define KVDC   256

#define OUT0   (T_NEWC*HIDC)
#define KOFF   OUT0
#define VOFF   (OUT0 + KVHC*T_FULLC*HDC)

#define ATT_SCALE 0.08838834764831845f  // 1/sqrt(128)

#define HID2 (T_NEWC*HIDC)
#define KV_ELEMS (KVHC*T_FULLC*HDC)     // 1,048,576

// ---------------- scratch ----------------
__device__ float g_q[HID2];
__device__ float g_attn[HID2];
__device__ float g_kn[T_NEWC*KVDC];
__device__ float g_vn[T_NEWC*KVDC];
__device__ uint4 g_kt4[KV_ELEMS/4];                          // K cache, tf32 [kh][t][d]
__device__ uint4 g_vth4[KV_ELEMS/8], g_vtl4[KV_ELEMS/8];     // V^T bf16 hi/lo [kh*128+d][4096]

// ---------------- helpers ----------------
__device__ __forceinline__ unsigned pack_bf2(__nv_bfloat16 a, __nv_bfloat16 b) {
    __nv_bfloat162 t = __halves2bfloat162(a, b);
    return *reinterpret_cast<unsigned*>(&t);
}
__device__ __forceinline__ void split2(float x, float y, unsigned& hi, unsigned& lo) {
    __nv_bfloat16 xh = __float2bfloat16_rn(x);
    __nv_bfloat16 yh = __float2bfloat16_rn(y);
    __nv_bfloat16 xl = __float2bfloat16_rn(x - __bfloat162float(xh));
    __nv_bfloat16 yl = __float2bfloat16_rn(y - __bfloat162float(yh));
    hi = pack_bf2(xh, yh);
    lo = pack_bf2(xl, yl);
}
__device__ __forceinline__ void mma_bf16(float* c, const unsigned* a, unsigned b0, unsigned b1) {
    asm volatile(
        "mma.sync.aligned.m16n8k16.row.col.f32.bf16.bf16.f32 "
        "{%0,%1,%2,%3}, {%4,%5,%6,%7}, {%8,%9}, {%0,%1,%2,%3};\n"
        : "+f"(c[0]), "+f"(c[1]), "+f"(c[2]), "+f"(c[3])
        : "r"(a[0]), "r"(a[1]), "r"(a[2]), "r"(a[3]), "r"(b0), "r"(b1));
}
__device__ __forceinline__ void mma_tf32(float* c, const unsigned* a, unsigned b0, unsigned b1) {
    asm volatile(
        "mma.sync.aligned.m16n8k8.row.col.f32.tf32.tf32.f32 "
        "{%0,%1,%2,%3}, {%4,%5,%6,%7}, {%8,%9}, {%0,%1,%2,%3};\n"
        : "+f"(c[0]), "+f"(c[1]), "+f"(c[2]), "+f"(c[3])
        : "r"(a[0]), "r"(a[1]), "r"(a[2]), "r"(a[3]), "r"(b0), "r"(b1));
}
__device__ __forceinline__ unsigned f2tf32(float x) {
    unsigned r;
    asm("cvt.rna.tf32.f32 %0, %1;\n" : "=r"(r) : "f"(x));
    return r;
}
__device__ __forceinline__ unsigned su32(const void* p) {
    return (unsigned)__cvta_generic_to_shared(p);
}
__device__ __forceinline__ void cpa16(u16* dst, const void* src) {
    asm volatile("cp.async.cg.shared.global [%0], [%1], 16;\n"
                 :: "r"(su32(dst)), "l"(src));
}
#define CP_COMMIT() asm volatile("cp.async.commit_group;\n")
#define CP_WAIT0()  asm volatile("cp.async.wait_group 0;\n")

__device__ __forceinline__ void ldsm4(unsigned r[4], const u16* rowbase, int stride, int kc) {
    const int lane = threadIdx.x & 31;
    const u16* p = rowbase + (lane & 15) * stride + kc + ((lane & 16) >> 1);
    unsigned a = su32(p);
    asm volatile("ldmatrix.sync.aligned.m8n8.x4.shared.b16 {%0,%1,%2,%3}, [%4];\n"
        : "=r"(r[0]), "=r"(r[1]), "=r"(r[2]), "=r"(r[3]) : "r"(a));
}

// ---------------------------------------------------------------------------
// tf32 GEMM (proven at R9): C = A @ W^T + bias. 128 thr, 2x2 warps,
// warp tile 64x64, CTA 128x128, BK=32. Region-dispatched for fused QKV.
// ---------------------------------------------------------------------------
__global__ __launch_bounds__(128, 2) void gemm_tf32(
    const float* __restrict__ A,
    const float* __restrict__ W0, const float* __restrict__ b0, float* __restrict__ C0,
    const float* __restrict__ W1, const float* __restrict__ b1, float* __restrict__ C1,
    const float* __restrict__ W2, const float* __restrict__ b2, float* __restrict__ C2,
    int nx0, int K)
{
    __shared__ unsigned As[128*36], Bs[128*36];

    const int tid  = threadIdx.x;
    const int w    = tid >> 5;
    const int lane = tid & 31;
    const int g    = lane >> 2;
    const int tig  = lane & 3;
    const int wm   = w >> 1, wn = w & 1;
    const int bm   = blockIdx.y * 128;
    const int bx   = blockIdx.x;

    const float *W, *bias; float* C; int N, bnl;
    if (bx < nx0)            { W = W0; bias = b0; C = C0; N = nx0*128; bnl = bx*128; }
    else if (bx < nx0 + 2)   { W = W1; bias = b1; C = C1; N = 256; bnl = (bx-nx0)*128; }
    else                     { W = W2; bias = b2; C = C2; N = 256; bnl = (bx-nx0-2)*128; }
    const float* Wp = W + (size_t)bnl * K;

    float acc[4][8][4];
    #pragma unroll
    for (int mt = 0; mt < 4; mt++)
        #pragma unroll
        for (int nt = 0; nt < 8; nt++)
            #pragma unroll
            for (int c = 0; c < 4; c++) acc[mt][nt][c] = 0.f;

    for (int k0 = 0; k0 < K; k0 += 32) {
        __syncthreads();
        #pragma unroll
        for (int it = 0; it < 8; it++) {
            int i = tid + it * 128;
            int row = i >> 3;
            int col = (i & 7) * 4;
            float4 a = *(const float4*)(A + (size_t)(bm + row) * K + k0 + col);
            *(uint4*)(As + row*36 + col) =
                make_uint4(f2tf32(a.x), f2tf32(a.y), f2tf32(a.z), f2tf32(a.w));
            float4 b = *(const float4*)(Wp + (size_t)row * K + k0 + col);
            *(uint4*)(Bs + row*36 + col) =
                make_uint4(f2tf32(b.x), f2tf32(b.y), f2tf32(b.z), f2tf32(b.w));
        }
        __syncthreads();

        #pragma unroll
        for (int kc = 0; kc < 4; kc++) {
            unsigned af[4][4];
            #pragma unroll
            for (int mt = 0; mt < 4; mt++)
                ldsm4(af[mt], (const u16*)As + (wm*64 + mt*16) * 72, 72, kc*16);
            #pragma unroll
            for (int ntp = 0; ntp < 4; ntp++) {
                unsigned bf[4];
                ldsm4(bf, (const u16*)Bs + (wn*64 + ntp*16) * 72, 72, kc*16);
                #pragma unroll
                for (int mt = 0; mt < 4; mt++) {
                    mma_tf32(acc[mt][2*ntp],   af[mt], bf[0], bf[2]);
                    mma_tf32(acc[mt][2*ntp+1], af[mt], bf[1], bf[3]);
                }
            }
        }
    }

    #pragma unroll
    for (int mt = 0; mt < 4; mt++) {
        #pragma unroll
        for (int nt = 0; nt < 8; nt++) {
            int row = bm + wm*64 + mt*16 + g;
            int col = bnl + wn*64 + nt*8 + 2*tig;
            float bb0 = bias[col], bb1 = bias[col+1];
            *(float2*)(C + (size_t)row * N + col) =
                make_float2(acc[mt][nt][0] + bb0, acc[mt][nt][1] + bb1);
            *(float2*)(C + (size_t)(row+8) * N + col) =
                make_float2(acc[mt][nt][2] + bb0, acc[mt][nt][3] + bb1);
        }
    }
}

// ---------------------------------------------------------------------------
// prep_k: concat K cache -> out fp32 + tf32 K cache (cvt.rna once)
// ---------------------------------------------------------------------------
__global__ __launch_bounds__(256) void prep_k(
    const float* __restrict__ pk, float* __restrict__ out)
{
    const int tid = threadIdx.x;
    const int h   = blockIdx.y;
    const int t0  = blockIdx.x * 64;
    unsigned* kt = (unsigned*)g_kt4;

    #pragma unroll
    for (int it = 0; it < 8; it++) {
        int i = tid + it * 256;
        int row = i >> 5, seg = i & 31;
        int t = t0 + row, d = seg * 4;
        float4 k4;
        if (t < T_PASTC) {
            k4 = *(const float4*)(pk + ((size_t)h * T_PASTC + t) * HDC + d);
        } else {
            k4 = *(const float4*)(g_kn + (size_t)(t - T_PASTC) * KVDC + h * HDC + d);
        }
        size_t oidx = ((size_t)h * T_FULLC + t) * HDC + d;
        *(float4*)(out + KOFF + oidx) = k4;
        *(uint4*)(kt + oidx) =
            make_uint4(f2tf32(k4.x), f2tf32(k4.y), f2tf32(k4.z), f2tf32(k4.w));
    }
}

// ---------------------------------------------------------------------------
// prep_v (unchanged, proven): concat V -> out fp32 + transposed bf16 hi/lo V^T
// ---------------------------------------------------------------------------
__global__ __launch_bounds__(256) void prep_v(
    const float* __restrict__ pv, float* __restrict__ out)
{
    __shared__ float Vsm[64][129];
    const int tid = threadIdx.x;
    const int h   = blockIdx.y;
    const int t0  = blockIdx.x * 64;
    uint2* vth = (uint2*)g_vth4;
    uint2* vtl = (uint2*)g_vtl4;

    #pragma unroll
    for (int it = 0; it < 8; it++) {
        int i = tid + it * 256;
        int row = i >> 5, seg = i & 31;
        int t = t0 + row, d = seg * 4;
        float4 v4;
        if (t < T_PASTC) {
            v4 = *(const float4*)(pv + ((size_t)h * T_PASTC + t) * HDC + d);
        } else {
            v4 = *(const float4*)(g_vn + (size_t)(t - T_PASTC) * KVDC + h * HDC + d);
        }
        size_t oidx = ((size_t)h * T_FULLC + t) * HDC + d;
        *(float4*)(out + VOFF + oidx) = v4;
        Vsm[row][d]   = v4.x; Vsm[row][d+1] = v4.y;
        Vsm[row][d+2] = v4.z; Vsm[row][d+3] = v4.w;
    }
    __syncthreads();

    #pragma unroll
    for (int it = 0; it < 16; it++) {
        int i = tid + it * 256;
        int split = i >> 11;
        int d = (i >> 4) & 127;
        int seg = i & 15;
        int tl = seg * 4;
        float v0 = Vsm[tl+0][d], v1 = Vsm[tl+1][d], v2 = Vsm[tl+2][d], v3 = Vsm[tl+3][d];
        unsigned h0, l0, h1, l1;
        split2(v0, v1, h0, l0);
        split2(v2, v3, h1, l1);
        size_t oidx = ((size_t)(h*128 + d) * T_FULLC + t0 + tl) >> 2;
        if (split == 0) vth[oidx] = make_uint2(h0, h1);
        else            vtl[oidx] = make_uint2(l0, l1);
    }
}

// ---------------------------------------------------------------------------
// Flash v4: tf32 S-stage (single pass), bf16x3 PV, BM=64, BN=64, 4 warps,
// 2 CTA/SM, 3-buffer cp.async ring.
// K tile: 64 rows x 136 fp32 (stride 272 halves), 34816 B.
// V tile: bf16 hi/lo as before, 36864 B.
// ---------------------------------------------------------------------------
#define FL3_BUF   18432                 // u16 per ring buffer (36,864 B)
#define FL3_BYTES (3*FL3_BUF*2)

__device__ __forceinline__ void fl4_load_k(u16* dst, int kh, int n0, int tid) {
    const unsigned* Kt = (const unsigned*)g_kt4;
    #pragma unroll
    for (int it = 0; it < 16; it++) {
        int i = tid + it * 128;          // 0..2047 16B chunks
        int row = i >> 5, seg = i & 31;
        const unsigned* src = Kt + (((size_t)(kh * T_FULLC + n0 + row)) << 7) + seg * 4;
        cpa16(dst + row * 272 + seg * 8, src);
    }
}
__device__ __forceinline__ void fl4_load_v(u16* dst, int kh, int n0, int tid) {
    const u16* Vh_g = (const u16*)g_vth4;
    const u16* Vl_g = (const u16*)g_vtl4;
    #pragma unroll
    for (int it = 0; it < 16; it++) {
        int i = tid + it * 128;
        int split = i >> 10;
        int j = i & 1023;
        int row = j >> 3, seg = j & 7;
        const u16* src = (split ? Vl_g : Vh_g)
                         + (((size_t)(kh * 128 + row)) << 12) + n0 + seg * 8;
        cpa16(dst + split * 9216 + row * 72 + seg * 8, src);
    }
}

__global__ __launch_bounds__(128, 2) void flash4()
{
    extern __shared__ u16 fsm[];
    u16* bufs[3] = { fsm, fsm + FL3_BUF, fsm + 2*FL3_BUF };

    const int tid  = threadIdx.x;
    const int w    = tid >> 5;
    const int lane = tid & 31;
    const int g    = lane >> 2;
    const int tig  = lane & 3;
    const int qi = (int)(gridDim.x - 1) - (int)blockIdx.x;   // heavy tiles first
    const int h  = blockIdx.y;
    const int qbase = qi * 64;
    const int kh = h >> 3;
    const int nkt = 33 + qi;

    // ---- stage Q (scaled, tf32) into bufs[0], extract 16 k8 fragments ----
    #pragma unroll
    for (int it = 0; it < 16; it++) {
        int i = tid + it * 128;
        int row = i >> 5, d = (i & 31) * 4;
        float4 q4 = *(const float4*)(g_q + (size_t)(qbase + row) * HIDC + h * HDC + d);
        *(uint4*)(bufs[0] + row*272 + d*2) =
            make_uint4(f2tf32(q4.x * ATT_SCALE), f2tf32(q4.y * ATT_SCALE),
                       f2tf32(q4.z * ATT_SCALE), f2tf32(q4.w * ATT_SCALE));
    }
    __syncthreads();
    unsigned qf[16][4];
    #pragma unroll
    for (int kc = 0; kc < 16; kc++)
        ldsm4(qf[kc], bufs[0] + (w*16) * 272, 272, kc * 16);
    __syncthreads();

    // ---- preload K(0)->buf0, V(0)->buf1 ----
    fl4_load_k(bufs[0], kh, 0, tid);
    fl4_load_v(bufs[1], kh, 0, tid);
    CP_COMMIT();

    float accO[16][4];
    #pragma unroll
    for (int dt = 0; dt < 16; dt++)
        #pragma unroll
        for (int c = 0; c < 4; c++) accO[dt][c] = 0.f;
    float m0 = -INFINITY, m1 = -INFINITY, l0s = 0.f, l1s = 0.f;

    int kbi = 0;
    for (int kt = 0; kt < nkt; kt++) {
        const u16* KB = bufs[kbi];
        const int vbi = (kbi + 1) % 3;
        const u16* VB = bufs[vbi];

        CP_WAIT0();
        __syncthreads();

        // ---- S = Q K^T (tf32 single pass: 16 k8 chunks) ----
        float s[8][4];
        #pragma unroll
        for (int nt = 0; nt < 8; nt++)
            #pragma unroll
            for (int c = 0; c < 4; c++) s[nt][c] = 0.f;

        #pragma unroll
        for (int kc = 0; kc < 16; kc++) {
            #pragma unroll
            for (int ntp = 0; ntp < 4; ntp++) {
                unsigned kf[4];
                ldsm4(kf, KB + ntp*16 * 272, 272, kc * 16);
                mma_tf32(s[2*ntp],   qf[kc], kf[0], kf[2]);
                mma_tf32(s[2*ntp+1], qf[kc], kf[1], kf[3]);
            }
        }
        __syncthreads();   // all warps done reading K(t)

        // ---- prefetch K(t+1), V(t+1) ----
        if (kt + 1 < nkt) {
            int kbn = (kbi + 2) % 3;
            fl4_load_k(bufs[kbn], kh, (kt + 1) * 64, tid);
            fl4_load_v(bufs[kbi], kh, (kt + 1) * 64, tid);
            CP_COMMIT();
        }

        // ---- causal mask (diagonal tile) ----
        if (kt == nkt - 1) {
            int r0 = w*16 + g, r1 = r0 + 8;
            #pragma unroll
            for (int nt = 0; nt < 8; nt++) {
                int cb = nt*8 + 2*tig;
                if (cb     > r0) s[nt][0] = -1e30f;
                if (cb + 1 > r0) s[nt][1] = -1e30f;
                if (cb     > r1) s[nt][2] = -1e30f;
                if (cb + 1 > r1) s[nt][3] = -1e30f;
            }
        }

        // ---- online softmax (registers) ----
        float mx0 = -1e30f, mx1 = -1e30f;
        #pragma unroll
        for (int nt = 0; nt < 8; nt++) {
            mx0 = fmaxf(mx0, fmaxf(s[nt][0], s[nt][1]));
            mx1 = fmaxf(mx1, fmaxf(s[nt][2], s[nt][3]));
        }
        mx0 = fmaxf(mx0, __shfl_xor_sync(0xffffffffu, mx0, 1));
        mx0 = fmaxf(mx0, __shfl_xor_sync(0xffffffffu, mx0, 2));
        mx1 = fmaxf(mx1, __shfl_xor_sync(0xffffffffu, mx1, 1));
        mx1 = fmaxf(mx1, __shfl_xor_sync(0xffffffffu, mx1, 2));
        float mn0 = fmaxf(m0, mx0), mn1 = fmaxf(m1, mx1);
        float f0 = __expf(m0 - mn0), f1 = __expf(m1 - mn1);
        float sum0 = 0.f, sum1 = 0.f;
        #pragma unroll
        for (int nt = 0; nt < 8; nt++) {
            s[nt][0] = __expf(s[nt][0] - mn0); sum0 += s[nt][0];
            s[nt][1] = __expf(s[nt][1] - mn0); sum0 += s[nt][1];
            s[nt][2] = __expf(s[nt][2] - mn1); sum1 += s[nt][2];
            s[nt][3] = __expf(s[nt][3] - mn1); sum1 += s[nt][3];
        }
        sum0 += __shfl_xor_sync(0xffffffffu, sum0, 1);
        sum0 += __shfl_xor_sync(0xffffffffu, sum0, 2);
        sum1 += __shfl_xor_sync(0xffffffffu, sum1, 1);
        sum1 += __shfl_xor_sync(0xffffffffu, sum1, 2);
        l0s = l0s * f0 + sum0;
        l1s = l1s * f1 + sum1;
        m0 = mn0; m1 = mn1;

        #pragma unroll
        for (int dt = 0; dt < 16; dt++) {
            accO[dt][0] *= f0; accO[dt][1] *= f0;
            accO[dt][2] *= f1; accO[dt][3] *= f1;
        }

        // ---- O += P V  (bf16x3, per-kc2 phi/plo) ----
        #pragma unroll
        for (int kc2 = 0; kc2 < 4; kc2++) {
            unsigned phi[4], plo[4];
            split2(s[2*kc2][0],   s[2*kc2][1],   phi[0], plo[0]);
            split2(s[2*kc2][2],   s[2*kc2][3],   phi[1], plo[1]);
            split2(s[2*kc2+1][0], s[2*kc2+1][1], phi[2], plo[2]);
            split2(s[2*kc2+1][2], s[2*kc2+1][3], phi[3], plo[3]);
            #pragma unroll
            for (int dtp = 0; dtp < 8; dtp++) {
                unsigned vh[4], vl[4];
                ldsm4(vh, VB + dtp*16 * 72, 72, kc2 * 16);
                ldsm4(vl, VB + 9216 + dtp*16 * 72, 72, kc2 * 16);
                mma_bf16(accO[2*dtp],   phi, vh[0], vh[2]);
                mma_bf16(accO[2*dtp],   phi, vl[0], vl[2]);
                mma_bf16(accO[2*dtp],   plo, vh[0], vh[2]);
                mma_bf16(accO[2*dtp+1], phi, vh[1], vh[3]);
                mma_bf16(accO[2*dtp+1], phi, vl[1], vl[3]);
                mma_bf16(accO[2*dtp+1], plo, vh[1], vh[3]);
            }
        }
        kbi = (kbi + 2) % 3;
    }

    float inv0 = 1.f / l0s, inv1 = 1.f / l1s;
    int row0 = qbase + w*16 + g;
    #pragma unroll
    for (int dt = 0; dt < 16; dt++) {
        int col = h * HDC + dt*8 + 2*tig;
        *(float2*)(g_attn + (size_t)row0 * HIDC + col) =
            make_float2(accO[dt][0] * inv0, accO[dt][1] * inv0);
        *(float2*)(g_attn + (size_t)(row0+8) * HIDC + col) =
            make_float2(accO[dt][2] * inv1, accO[dt][3] * inv1);
    }
}

// ---------------------------------------------------------------------------
extern "C" void kernel_launch(void* const* d_in, const int* in_sizes, int n_in,
                              void* d_out, int out_size)
{
    const float* hs     = (const float*)d_in[0];
    const float* past_k = (const float*)d_in[2];
    const float* past_v = (const float*)d_in[3];
    const float* q_w    = (const float*)d_in[4];
    const float* q_b    = (const float*)d_in[5];
    const float* k_w    = (const float*)d_in[6];
    const float* k_b    = (const float*)d_in[7];
    const float* v_w    = (const float*)d_in[8];
    const float* v_b    = (const float*)d_in[9];
    const float* o_w    = (const float*)d_in[10];
    const float* o_b    = (const float*)d_in[11];
    float* out = (float*)d_out;

    void *gq, *gattn, *gkn, *gvn;
    cudaGetSymbolAddress(&gq,  g_q);   cudaGetSymbolAddress(&gattn, g_attn);
    cudaGetSymbolAddress(&gkn, g_kn);  cudaGetSymbolAddress(&gvn,  g_vn);

    cudaFuncSetAttribute(flash4, cudaFuncAttributeMaxDynamicSharedMemorySize, FL3_BYTES);

    // [1] fused Q/K/V projections (tf32)
    gemm_tf32<<<dim3(20, 16), 128>>>(
        hs,
        q_w, q_b, (float*)gq,
        k_w, k_b, (float*)gkn,
        v_w, v_b, (float*)gvn,
        16, HIDC);

    // [2][3] KV concat + caches (K -> tf32, V -> bf16 hi/lo transposed)
    prep_k<<<dim3(T_FULLC/64, KVHC), 256>>>(past_k, out);
    prep_v<<<dim3(T_FULLC/64, KVHC), 256>>>(past_v, out);

    // [4] attention (tf32 S, bf16x3 PV)
    flash4<<<dim3(T_NEWC/64, NHC), 128, FL3_BYTES>>>();

    // [5] O projection (tf32)
    gemm_tf32<<<dim3(16, 16), 128>>>(
        (const float*)gattn,
        o_w, o_b, out,
        nullptr, nullptr, nullptr,
        nullptr, nullptr, nullptr,
        16, HIDC);
}